// round 9
// baseline (speedup 1.0000x reference)
#include <cuda_runtime.h>
#include <cuda_fp16.h>
#include <cstdint>

#define HW    65536
#define CCH   64
#define NPIX  (16 * HW)            // 1,048,576 pixels
#define NTOT  (16 * CCH * HW)      // 67,108,864 elements

// ---------------- device scratch (allocation-free) ---------------------------
__device__ __half   g_bufA[NTOT];
__device__ __half   g_bufB[NTOT];
__device__ __half   g_bufC[NTOT];     // fp16 shadow of x
__device__ unsigned g_amax[4];        // abs-max bits of: x, y1, y3, y4 (idempotent)
__device__ float    g_wscale[4];      // scales of: w_p1, w_f1, w_p2, w_f2
__device__ int      g_qwp[2][1024];   // packed int8 pointwise weights [co][ci/4]
__device__ int      g_qwfi[2][192];   // packed int8 dw weight rows [c][3] = (w0,w1,w2,0)

// ---------------- init: weight prep (blocks 0-3) + absmax/x16 (rest) ---------
__global__ void __launch_bounds__(256) k_init(const float4* __restrict__ x, int nvec,
                                              const float* __restrict__ wp1,
                                              const float* __restrict__ wf1,
                                              const float* __restrict__ wp2,
                                              const float* __restrict__ wf2)
{
    if (blockIdx.x < 4) {
        int b = blockIdx.x;   // 0:wp1 1:wf1 2:wp2 3:wf2
        const float* w = (b == 0) ? wp1 : (b == 1) ? wf1 : (b == 2) ? wp2 : wf2;
        int n = (b & 1) ? 576 : 4096;

        __shared__ float red[256];
        float m = 0.f;
        for (int i = threadIdx.x; i < n; i += 256) m = fmaxf(m, fabsf(w[i]));
        red[threadIdx.x] = m;
        __syncthreads();
        for (int s = 128; s > 0; s >>= 1) {
            if (threadIdx.x < s) red[threadIdx.x] = fmaxf(red[threadIdx.x], red[threadIdx.x + s]);
            __syncthreads();
        }
        __shared__ float s_scale;
        if (threadIdx.x == 0) {
            float sc = red[0] / 7.0f + 1e-12f;
            g_wscale[b] = sc;
            s_scale = sc;
        }
        __syncthreads();
        float sc = s_scale;

        if (b & 1) {
            for (int i = threadIdx.x; i < 192; i += 256) {
                const float* wr = w + (i / 3) * 9 + (i % 3) * 3;
                int q0 = (int)fminf(fmaxf(rintf(wr[0] / sc), -7.f), 7.f);
                int q1 = (int)fminf(fmaxf(rintf(wr[1] / sc), -7.f), 7.f);
                int q2 = (int)fminf(fmaxf(rintf(wr[2] / sc), -7.f), 7.f);
                g_qwfi[b >> 1][i] = (q0 & 0xFF) | ((q1 & 0xFF) << 8) | ((q2 & 0xFF) << 16);
            }
        } else {
            for (int i = threadIdx.x; i < 1024; i += 256) {
                int word = 0;
                #pragma unroll
                for (int j = 0; j < 4; j++) {
                    float q = fminf(fmaxf(rintf(w[i * 4 + j] / sc), -7.f), 7.f);
                    word |= ((int)q & 0xFF) << (8 * j);
                }
                g_qwp[b >> 1][i] = word;
            }
        }
        return;
    }

    // ---- absmax(x) + fp16 shadow copy ----
    uint2* __restrict__ c16 = reinterpret_cast<uint2*>(g_bufC);
    int stride = (gridDim.x - 4) * 256;
    float m = 0.f;
    for (int i = (blockIdx.x - 4) * 256 + threadIdx.x; i < nvec; i += stride) {
        float4 v = __ldcs(&x[i]);
        __half2 h01 = __floats2half2_rn(v.x, v.y);
        __half2 h23 = __floats2half2_rn(v.z, v.w);
        uint2 st;
        st.x = *reinterpret_cast<unsigned*>(&h01);
        st.y = *reinterpret_cast<unsigned*>(&h23);
        c16[i] = st;
        m = fmaxf(m, fmaxf(fmaxf(fabsf(v.x), fabsf(v.y)), fmaxf(fabsf(v.z), fabsf(v.w))));
    }
    #pragma unroll
    for (int off = 16; off; off >>= 1) m = fmaxf(m, __shfl_xor_sync(0xFFFFFFFFu, m, off));
    __shared__ float wm[8];
    int lane = threadIdx.x & 31, wid = threadIdx.x >> 5;
    if (lane == 0) wm[wid] = m;
    __syncthreads();
    if (threadIdx.x == 0) {
        float mm = wm[0];
        #pragma unroll
        for (int i = 1; i < 8; i++) mm = fmaxf(mm, wm[i]);
        atomicMax(&g_amax[0], __float_as_uint(mm));
    }
}

// ---------------- pointwise 1x1 conv via tensor-core IMMA --------------------
// WHICH 0: in = bufC (half x), out = bufA (half), amax 0 -> 1
// WHICH 1: in = bufB (half),   out = bufA (half), amax 2 -> 3
// Block: 256 thr, 128 pixels. Warp w handles px tile [16w, 16w+16).
// mma.sync.aligned.m16n8k32.row.col.s32.s8.s8.s32, K=64 as 2 chunks of 32.
#define SAW 17      // smem A row pitch in words (64B data + 4B pad)
#define SCW 70      // smem C row pitch in halves (128 data + 12 pad)
template<int WHICH>
__global__ void __launch_bounds__(256) k_pw()
{
    __shared__ __align__(16) int     ws[1024];
    __shared__ __align__(16) int     sA[128 * SAW];          // [px][ci-word] int8x4
    __shared__ __align__(4)  unsigned short sC[128 * SCW];   // [px][co] half

    int t = threadIdx.x;
    for (int i = t; i < 1024; i += 256) ws[i] = g_qwp[WHICH][i];

    float in_max = __uint_as_float(g_amax[WHICH * 2]);
    float s_in = in_max * (1.0f / 127.0f) + 1e-12f;
    float inv  = 1.0f / s_in;
    float osc  = s_in * g_wscale[WHICH * 2];

    unsigned pxg  = blockIdx.x * 128u;
    unsigned hw   = pxg & 0xFFFFu;
    unsigned bbase = (pxg >> 16) * (CCH * HW) + hw;
    const __half* in = (WHICH == 0) ? g_bufC : g_bufB;

    // ---- stage 1: load fp16, quantize, transpose 4ch x 8px, store [px][ci] --
    {
        int cg = t >> 4;            // channel group 0..15 (channels 4cg..4cg+3)
        int ps = (t & 15) << 3;     // local px 0..120 step 8
        unsigned Wlo[4], Whi[4];
        #pragma unroll
        for (int j = 0; j < 4; j++) {
            uint4 raw = *reinterpret_cast<const uint4*>(in + bbase + (unsigned)(4 * cg + j) * HW + ps);
            float2 f0 = __half22float2(*reinterpret_cast<__half2*>(&raw.x));
            float2 f1 = __half22float2(*reinterpret_cast<__half2*>(&raw.y));
            float2 f2 = __half22float2(*reinterpret_cast<__half2*>(&raw.z));
            float2 f3 = __half22float2(*reinterpret_cast<__half2*>(&raw.w));
            int q0 = __float2int_rn(f0.x * inv), q1 = __float2int_rn(f0.y * inv);
            int q2 = __float2int_rn(f1.x * inv), q3 = __float2int_rn(f1.y * inv);
            int q4 = __float2int_rn(f2.x * inv), q5 = __float2int_rn(f2.y * inv);
            int q6 = __float2int_rn(f3.x * inv), q7 = __float2int_rn(f3.y * inv);
            Wlo[j] = __byte_perm(__byte_perm(q0, q1, 0x0040),
                                 __byte_perm(q2, q3, 0x0040), 0x5410);
            Whi[j] = __byte_perm(__byte_perm(q4, q5, 0x0040),
                                 __byte_perm(q6, q7, 0x0040), 0x5410);
        }
        // transpose 4x4 bytes (channels x pixels) -> per-pixel ci words
        unsigned X01 = __byte_perm(Wlo[0], Wlo[1], 0x5140);
        unsigned X23 = __byte_perm(Wlo[2], Wlo[3], 0x5140);
        unsigned Y01 = __byte_perm(Wlo[0], Wlo[1], 0x7362);
        unsigned Y23 = __byte_perm(Wlo[2], Wlo[3], 0x7362);
        sA[(ps + 0) * SAW + cg] = __byte_perm(X01, X23, 0x5410);
        sA[(ps + 1) * SAW + cg] = __byte_perm(X01, X23, 0x7632);
        sA[(ps + 2) * SAW + cg] = __byte_perm(Y01, Y23, 0x5410);
        sA[(ps + 3) * SAW + cg] = __byte_perm(Y01, Y23, 0x7632);
        X01 = __byte_perm(Whi[0], Whi[1], 0x5140);
        X23 = __byte_perm(Whi[2], Whi[3], 0x5140);
        Y01 = __byte_perm(Whi[0], Whi[1], 0x7362);
        Y23 = __byte_perm(Whi[2], Whi[3], 0x7362);
        sA[(ps + 4) * SAW + cg] = __byte_perm(X01, X23, 0x5410);
        sA[(ps + 5) * SAW + cg] = __byte_perm(X01, X23, 0x7632);
        sA[(ps + 6) * SAW + cg] = __byte_perm(Y01, Y23, 0x5410);
        sA[(ps + 7) * SAW + cg] = __byte_perm(Y01, Y23, 0x7632);
    }
    __syncthreads();

    // ---- stage 2: IMMA -------------------------------------------------------
    float lmax = 0.f;
    {
        int w = t >> 5, lane = t & 31;
        int r = lane >> 2, q = lane & 3;
        int abase = (w * 16 + r) * SAW + q;
        int A0 = sA[abase],                A1 = sA[abase + 8 * SAW];
        int A2 = sA[abase + 4],            A3 = sA[abase + 4 + 8 * SAW];
        int A4 = sA[abase + 8],            A5 = sA[abase + 8 + 8 * SAW];
        int A6 = sA[abase + 12],           A7 = sA[abase + 12 + 8 * SAW];

        int crow0 = (w * 16 + r) * SCW;
        int crow1 = (w * 16 + r + 8) * SCW;
        #pragma unroll
        for (int nt = 0; nt < 8; nt++) {
            int co = nt * 8 + r;
            int b0 = ws[co * 16 + q],      b1 = ws[co * 16 + q + 4];
            int b2 = ws[co * 16 + q + 8],  b3 = ws[co * 16 + q + 12];
            int c0 = 0, c1 = 0, c2 = 0, c3 = 0;
            asm("mma.sync.aligned.m16n8k32.row.col.s32.s8.s8.s32 "
                "{%0,%1,%2,%3}, {%4,%5,%6,%7}, {%8,%9}, {%0,%1,%2,%3};"
                : "+r"(c0), "+r"(c1), "+r"(c2), "+r"(c3)
                : "r"(A0), "r"(A1), "r"(A2), "r"(A3), "r"(b0), "r"(b1));
            asm("mma.sync.aligned.m16n8k32.row.col.s32.s8.s8.s32 "
                "{%0,%1,%2,%3}, {%4,%5,%6,%7}, {%8,%9}, {%0,%1,%2,%3};"
                : "+r"(c0), "+r"(c1), "+r"(c2), "+r"(c3)
                : "r"(A4), "r"(A5), "r"(A6), "r"(A7), "r"(b2), "r"(b3));
            float y0 = (float)c0 * osc, y1 = (float)c1 * osc;
            float y2 = (float)c2 * osc, y3 = (float)c3 * osc;
            lmax = fmaxf(lmax, fmaxf(fmaxf(fabsf(y0), fabsf(y1)), fmaxf(fabsf(y2), fabsf(y3))));
            __half2 h01 = __floats2half2_rn(y0, y1);
            __half2 h23 = __floats2half2_rn(y2, y3);
            *reinterpret_cast<__half2*>(&sC[crow0 + nt * 8 + 2 * q]) = h01;
            *reinterpret_cast<__half2*>(&sC[crow1 + nt * 8 + 2 * q]) = h23;
        }
    }
    __syncthreads();

    // ---- stage 3: coalesced store [co][px] -----------------------------------
    {
        int co = t & 63, pq = t >> 6;       // pq: px quarter (32 px)
        unsigned gb = bbase + (unsigned)co * HW + pq * 32u;
        #pragma unroll
        for (int g2 = 0; g2 < 4; g2++) {
            int px = pq * 32 + g2 * 8;
            unsigned w0 = __byte_perm(sC[(px + 0) * SCW + co], sC[(px + 1) * SCW + co], 0x5410);
            unsigned w1 = __byte_perm(sC[(px + 2) * SCW + co], sC[(px + 3) * SCW + co], 0x5410);
            unsigned w2 = __byte_perm(sC[(px + 4) * SCW + co], sC[(px + 5) * SCW + co], 0x5410);
            unsigned w3 = __byte_perm(sC[(px + 6) * SCW + co], sC[(px + 7) * SCW + co], 0x5410);
            *reinterpret_cast<uint4*>(g_bufA + gb + g2 * 8) = make_uint4(w0, w1, w2, w3);
        }
    }

    // ---- amax reduction ------------------------------------------------------
    #pragma unroll
    for (int off = 16; off; off >>= 1) lmax = fmaxf(lmax, __shfl_xor_sync(0xFFFFFFFFu, lmax, off));
    __shared__ float wm[8];
    int lane = t & 31, wid = t >> 5;
    if (lane == 0) wm[wid] = lmax;
    __syncthreads();
    if (t == 0) {
        float mm = wm[0];
        #pragma unroll
        for (int i = 1; i < 8; i++) mm = fmaxf(mm, wm[i]);
        atomicMax(&g_amax[WHICH * 2 + 1], __float_as_uint(mm));
    }
}

// ---------------- depthwise 3x3 (exact int8 dp4a) + PReLU (+residual) --------
// WHICH 0: bufA(half) -> bufB(half), amax_in [1], fused amax_out [2]
// WHICH 1: bufA(half) -> dout(fp32) + residual bufC(half x), amax_in [3]
template<int WHICH>
__global__ void __launch_bounds__(128) k_dw(float* __restrict__ dout,
                                            const float* __restrict__ alpha)
{
    int bc    = blockIdx.x >> 2;     // 0..1023
    int strip = blockIdx.x & 3;
    int c     = bc & 63;
    int warp  = threadIdx.x >> 5;
    int lane  = threadIdx.x & 31;
    int rbase = strip * 64 + warp * 16;
    int col0  = lane * 8;

    float in_max = __uint_as_float(g_amax[WHICH == 0 ? 1 : 3]);
    float s_in = in_max * (1.0f / 127.0f) + 1e-12f;
    float inv  = 1.0f / s_in;
    float osc  = s_in * g_wscale[WHICH == 0 ? 1 : 3];   // int acc -> fp value

    int wr0 = g_qwfi[WHICH][c * 3 + 0];
    int wr1 = g_qwfi[WHICH][c * 3 + 1];
    int wr2 = g_qwfi[WHICH][c * 3 + 2];
    float a = alpha[c];

    const __half* in = g_bufA + (unsigned)bc * HW;
    int accT[8], accM[8];
    #pragma unroll
    for (int j = 0; j < 8; j++) { accT[j] = 0; accM[j] = 0; }
    float lmax = 0.f;

    uint4 nxt;
    {
        int rr = rbase - 1;
        nxt = (rr >= 0) ? *reinterpret_cast<const uint4*>(in + rr * 256 + col0)
                        : make_uint4(0, 0, 0, 0);
    }

    #pragma unroll 3
    for (int k = 0; k < 18; k++) {
        uint4 raw = nxt;
        int rr = rbase - 1 + k;
        bool valid = (rr >= 0 && rr < 256);
        if (k < 17) {                      // prefetch next row
            int rn = rbase + k;
            nxt = (rn < 256) ? *reinterpret_cast<const uint4*>(in + rn * 256 + col0)
                             : make_uint4(0, 0, 0, 0);
        }

        unsigned wA = 0, wB = 0;
        if (valid) {
            float2 f0 = __half22float2(*reinterpret_cast<__half2*>(&raw.x));
            float2 f1 = __half22float2(*reinterpret_cast<__half2*>(&raw.y));
            float2 f2 = __half22float2(*reinterpret_cast<__half2*>(&raw.z));
            float2 f3 = __half22float2(*reinterpret_cast<__half2*>(&raw.w));
            int q0 = __float2int_rn(f0.x * inv), q1 = __float2int_rn(f0.y * inv);
            int q2 = __float2int_rn(f1.x * inv), q3 = __float2int_rn(f1.y * inv);
            int q4 = __float2int_rn(f2.x * inv), q5 = __float2int_rn(f2.y * inv);
            int q6 = __float2int_rn(f3.x * inv), q7 = __float2int_rn(f3.y * inv);
            wA = __byte_perm(__byte_perm(q0, q1, 0x0040),
                             __byte_perm(q2, q3, 0x0040), 0x5410);
            wB = __byte_perm(__byte_perm(q4, q5, 0x0040),
                             __byte_perm(q6, q7, 0x0040), 0x5410);
        }
        unsigned wPrev = __shfl_up_sync(0xFFFFFFFFu, wB, 1);
        unsigned wNext = __shfl_down_sync(0xFFFFFFFFu, wA, 1);
        if (lane == 0)  wPrev = 0;    // image left edge
        if (lane == 31) wNext = 0;    // image right edge

        // 8 sliding windows: bytes (q[j-1], q[j], q[j+1], X) — X hits weight 0
        unsigned win[8];
        win[0] = __byte_perm(wPrev, wA, 0x0543);
        win[1] = wA;
        win[2] = __byte_perm(wA, wB, 0x4321);
        win[3] = __byte_perm(wA, wB, 0x5432);
        win[4] = __byte_perm(wA, wB, 0x6543);
        win[5] = wB;
        win[6] = __byte_perm(wB, wNext, 0x4321);
        win[7] = __byte_perm(wB, wNext, 0x5432);

        if (k >= 2) {
            int ro = rbase + k - 2;
            unsigned off = (unsigned)bc * HW + (unsigned)(ro * 256 + col0);
            float y[8];
            #pragma unroll
            for (int j = 0; j < 8; j++) {
                int acc = __dp4a((int)win[j], wr2, accM[j]);
                float v = (float)acc * osc;
                y[j] = (v > 0.f) ? v : a * v;
            }
            if (WHICH == 0) {
                #pragma unroll
                for (int j = 0; j < 8; j++) lmax = fmaxf(lmax, fabsf(y[j]));
                uint4 st;
                __half2 h0 = __floats2half2_rn(y[0], y[1]);
                __half2 h1 = __floats2half2_rn(y[2], y[3]);
                __half2 h2 = __floats2half2_rn(y[4], y[5]);
                __half2 h3 = __floats2half2_rn(y[6], y[7]);
                st.x = *reinterpret_cast<unsigned*>(&h0);
                st.y = *reinterpret_cast<unsigned*>(&h1);
                st.z = *reinterpret_cast<unsigned*>(&h2);
                st.w = *reinterpret_cast<unsigned*>(&h3);
                *reinterpret_cast<uint4*>(g_bufB + off) = st;
            } else {
                uint4 rr16 = *reinterpret_cast<const uint4*>(g_bufC + off);
                float2 r0 = __half22float2(*reinterpret_cast<__half2*>(&rr16.x));
                float2 r1 = __half22float2(*reinterpret_cast<__half2*>(&rr16.y));
                float2 r2 = __half22float2(*reinterpret_cast<__half2*>(&rr16.z));
                float2 r3 = __half22float2(*reinterpret_cast<__half2*>(&rr16.w));
                float4 o0, o1;
                o0.x = y[0] + r0.x; o0.y = y[1] + r0.y;
                o0.z = y[2] + r1.x; o0.w = y[3] + r1.y;
                o1.x = y[4] + r2.x; o1.y = y[5] + r2.y;
                o1.z = y[6] + r3.x; o1.w = y[7] + r3.y;
                __stcs(reinterpret_cast<float4*>(dout + off), o0);
                __stcs(reinterpret_cast<float4*>(dout + off + 4), o1);
            }
        }
        #pragma unroll
        for (int j = 0; j < 8; j++) {
            accM[j] = __dp4a((int)win[j], wr1, accT[j]);
            accT[j] = __dp4a((int)win[j], wr0, 0);
        }
    }

    if (WHICH == 0) {
        #pragma unroll
        for (int off = 16; off; off >>= 1) lmax = fmaxf(lmax, __shfl_xor_sync(0xFFFFFFFFu, lmax, off));
        __shared__ float wm[4];
        if (lane == 0) wm[warp] = lmax;
        __syncthreads();
        if (threadIdx.x == 0)
            atomicMax(&g_amax[2],
                      __float_as_uint(fmaxf(fmaxf(wm[0], wm[1]), fmaxf(wm[2], wm[3]))));
    }
}

// ---------------- launch ------------------------------------------------------
extern "C" void kernel_launch(void* const* d_in, const int* in_sizes, int n_in,
                              void* d_out, int out_size)
{
    const float* x      = (const float*)d_in[0];
    const float* w_p1   = (const float*)d_in[1];
    const float* w_f1   = (const float*)d_in[2];
    const float* w_p2   = (const float*)d_in[3];
    const float* w_f2   = (const float*)d_in[4];
    const float* alpha1 = (const float*)d_in[5];
    const float* alpha2 = (const float*)d_in[6];
    float* out = (float*)d_out;

    k_init<<<2052, 256>>>((const float4*)x, NTOT / 4, w_p1, w_f1, w_p2, w_f2);

    k_pw<0><<<NPIX / 128, 256>>>();              // bufC -> bufA, amax y1
    k_dw<0><<<4096, 128>>>(nullptr, alpha1);     // bufA -> bufB, amax y3
    k_pw<1><<<NPIX / 128, 256>>>();              // bufB -> bufA, amax y4
    k_dw<1><<<4096, 128>>>(out, alpha2);         // bufA -> out (+x16)
}

// round 10
// speedup vs baseline: 1.2426x; 1.2426x over previous
#include <cuda_runtime.h>
#include <cuda_fp16.h>
#include <cstdint>

#define HW    65536
#define CCH   64
#define NPIX  (16 * HW)            // 1,048,576 pixels
#define NTOT  (16 * CCH * HW)      // 67,108,864 elements

// ---------------- device scratch (allocation-free) ---------------------------
__device__ __half   g_bufA[NTOT];
__device__ __half   g_bufB[NTOT];
__device__ __half   g_bufC[NTOT];     // fp16 shadow of x
__device__ unsigned g_amax[4];        // abs-max bits of: x, y1, y3, y4 (idempotent)
__device__ float    g_wscale[4];      // scales of: w_p1, w_f1, w_p2, w_f2
__device__ int      g_qwp[2][1024];   // pw weights in IMMA B-fragment order
__device__ int      g_qwfi[2][192];   // packed int8 dw weight rows [c][3] = (w0,w1,w2,0)

// ---------------- init: weight prep (blocks 0-3) + absmax/x16 (rest) ---------
__global__ void __launch_bounds__(256) k_init(const float4* __restrict__ x, int nvec,
                                              const float* __restrict__ wp1,
                                              const float* __restrict__ wf1,
                                              const float* __restrict__ wp2,
                                              const float* __restrict__ wf2)
{
    if (blockIdx.x < 4) {
        int b = blockIdx.x;   // 0:wp1 1:wf1 2:wp2 3:wf2
        const float* w = (b == 0) ? wp1 : (b == 1) ? wf1 : (b == 2) ? wp2 : wf2;
        int n = (b & 1) ? 576 : 4096;

        __shared__ float red[256];
        float m = 0.f;
        for (int i = threadIdx.x; i < n; i += 256) m = fmaxf(m, fabsf(w[i]));
        red[threadIdx.x] = m;
        __syncthreads();
        for (int s = 128; s > 0; s >>= 1) {
            if (threadIdx.x < s) red[threadIdx.x] = fmaxf(red[threadIdx.x], red[threadIdx.x + s]);
            __syncthreads();
        }
        __shared__ float s_scale;
        if (threadIdx.x == 0) {
            float sc = red[0] / 7.0f + 1e-12f;
            g_wscale[b] = sc;
            s_scale = sc;
        }
        __syncthreads();
        float sc = s_scale;

        if (b & 1) {
            for (int i = threadIdx.x; i < 192; i += 256) {
                const float* wr = w + (i / 3) * 9 + (i % 3) * 3;
                int q0 = (int)fminf(fmaxf(rintf(wr[0] / sc), -7.f), 7.f);
                int q1 = (int)fminf(fmaxf(rintf(wr[1] / sc), -7.f), 7.f);
                int q2 = (int)fminf(fmaxf(rintf(wr[2] / sc), -7.f), 7.f);
                g_qwfi[b >> 1][i] = (q0 & 0xFF) | ((q1 & 0xFF) << 8) | ((q2 & 0xFF) << 16);
            }
        } else {
            // pointwise: pack words and store in IMMA B-fragment order:
            // idx = nt*128 + (r*4+q)*4 + m  for co = nt*8+r, kw = q+4m
            for (int i = threadIdx.x; i < 1024; i += 256) {
                int word = 0;
                #pragma unroll
                for (int j = 0; j < 4; j++) {
                    float q = fminf(fmaxf(rintf(w[i * 4 + j] / sc), -7.f), 7.f);
                    word |= ((int)q & 0xFF) << (8 * j);
                }
                int co = i >> 4, kw = i & 15;
                int nt = co >> 3, rr = co & 7, qq = kw & 3, mm = kw >> 2;
                g_qwp[b >> 1][nt * 128 + (rr * 4 + qq) * 4 + mm] = word;
            }
        }
        return;
    }

    // ---- absmax(x) + fp16 shadow copy ----
    uint2* __restrict__ c16 = reinterpret_cast<uint2*>(g_bufC);
    int stride = (gridDim.x - 4) * 256;
    float m = 0.f;
    for (int i = (blockIdx.x - 4) * 256 + threadIdx.x; i < nvec; i += stride) {
        float4 v = __ldcs(&x[i]);
        __half2 h01 = __floats2half2_rn(v.x, v.y);
        __half2 h23 = __floats2half2_rn(v.z, v.w);
        uint2 st;
        st.x = *reinterpret_cast<unsigned*>(&h01);
        st.y = *reinterpret_cast<unsigned*>(&h23);
        c16[i] = st;
        m = fmaxf(m, fmaxf(fmaxf(fabsf(v.x), fabsf(v.y)), fmaxf(fabsf(v.z), fabsf(v.w))));
    }
    #pragma unroll
    for (int off = 16; off; off >>= 1) m = fmaxf(m, __shfl_xor_sync(0xFFFFFFFFu, m, off));
    __shared__ float wm[8];
    int lane = threadIdx.x & 31, wid = threadIdx.x >> 5;
    if (lane == 0) wm[wid] = m;
    __syncthreads();
    if (threadIdx.x == 0) {
        float mm = wm[0];
        #pragma unroll
        for (int i = 1; i < 8; i++) mm = fmaxf(mm, wm[i]);
        atomicMax(&g_amax[0], __float_as_uint(mm));
    }
}

// ---------------- pointwise 1x1 conv via tensor-core IMMA --------------------
// WHICH 0: in = bufC (half x), out = bufA (half), amax 0 -> 1
// WHICH 1: in = bufB (half),   out = bufA (half), amax 2 -> 3
// 256 thr / 128 px per block. Warp w: px tile [16w, 16w+16).
// sA: [px][kw] with XOR swizzle; C: stmatrix.trans -> sC [co][px], pitch 136 halves.
#define SCP 136
template<int WHICH>
__global__ void __launch_bounds__(256) k_pw()
{
    __shared__ __align__(16) int sA[128 * 16];                 // 8 KB
    __shared__ __align__(16) unsigned short sC[64 * SCP];      // 17408 B

    int t = threadIdx.x;
    int lane = t & 31;

    float in_max = __uint_as_float(g_amax[WHICH * 2]);
    float s_in = in_max * (1.0f / 127.0f) + 1e-12f;
    float inv  = 1.0f / s_in;
    float osc  = s_in * g_wscale[WHICH * 2];

    unsigned pxg  = blockIdx.x * 128u;
    unsigned bbase = (pxg >> 16) * (CCH * HW) + (pxg & 0xFFFFu);
    const __half* in = (WHICH == 0) ? g_bufC : g_bufB;

    // B fragments: coalesced LDG.128, fragment order, into registers
    int4 Bf[8];
    {
        const int4* bfp = reinterpret_cast<const int4*>(g_qwp[WHICH]);
        #pragma unroll
        for (int nt = 0; nt < 8; nt++) Bf[nt] = bfp[nt * 32 + lane];
    }

    // ---- stage 1: load fp16, quantize, transpose 4ch x 8px, swizzled store --
    {
        int cg = t >> 4;            // channel group 0..15
        int i15 = t & 15;
        int ps = i15 << 3;          // px 0..120 step 8
        int swb = cg ^ i15;
        unsigned Wlo[4], Whi[4];
        #pragma unroll
        for (int j = 0; j < 4; j++) {
            uint4 raw = *reinterpret_cast<const uint4*>(in + bbase + (unsigned)(4 * cg + j) * HW + ps);
            float2 f0 = __half22float2(*reinterpret_cast<__half2*>(&raw.x));
            float2 f1 = __half22float2(*reinterpret_cast<__half2*>(&raw.y));
            float2 f2 = __half22float2(*reinterpret_cast<__half2*>(&raw.z));
            float2 f3 = __half22float2(*reinterpret_cast<__half2*>(&raw.w));
            int q0 = __float2int_rn(f0.x * inv), q1 = __float2int_rn(f0.y * inv);
            int q2 = __float2int_rn(f1.x * inv), q3 = __float2int_rn(f1.y * inv);
            int q4 = __float2int_rn(f2.x * inv), q5 = __float2int_rn(f2.y * inv);
            int q6 = __float2int_rn(f3.x * inv), q7 = __float2int_rn(f3.y * inv);
            Wlo[j] = __byte_perm(__byte_perm(q0, q1, 0x0040),
                                 __byte_perm(q2, q3, 0x0040), 0x5410);
            Whi[j] = __byte_perm(__byte_perm(q4, q5, 0x0040),
                                 __byte_perm(q6, q7, 0x0040), 0x5410);
        }
        unsigned X01 = __byte_perm(Wlo[0], Wlo[1], 0x5140);
        unsigned X23 = __byte_perm(Wlo[2], Wlo[3], 0x5140);
        unsigned Y01 = __byte_perm(Wlo[0], Wlo[1], 0x7362);
        unsigned Y23 = __byte_perm(Wlo[2], Wlo[3], 0x7362);
        sA[(ps + 0) * 16 + (swb ^ 0)]  = __byte_perm(X01, X23, 0x5410);
        sA[(ps + 1) * 16 + (swb ^ 2)]  = __byte_perm(X01, X23, 0x7632);
        sA[(ps + 2) * 16 + (swb ^ 4)]  = __byte_perm(Y01, Y23, 0x5410);
        sA[(ps + 3) * 16 + (swb ^ 6)]  = __byte_perm(Y01, Y23, 0x7632);
        X01 = __byte_perm(Whi[0], Whi[1], 0x5140);
        X23 = __byte_perm(Whi[2], Whi[3], 0x5140);
        Y01 = __byte_perm(Whi[0], Whi[1], 0x7362);
        Y23 = __byte_perm(Whi[2], Whi[3], 0x7362);
        sA[(ps + 4) * 16 + (swb ^ 8)]  = __byte_perm(X01, X23, 0x5410);
        sA[(ps + 5) * 16 + (swb ^ 10)] = __byte_perm(X01, X23, 0x7632);
        sA[(ps + 6) * 16 + (swb ^ 12)] = __byte_perm(Y01, Y23, 0x5410);
        sA[(ps + 7) * 16 + (swb ^ 14)] = __byte_perm(Y01, Y23, 0x7632);
    }
    __syncthreads();

    // ---- stage 2: IMMA + stmatrix.trans epilogue ----------------------------
    float lmax = 0.f;
    {
        int w = t >> 5;
        int r = lane >> 2, q = lane & 3;
        int W = w * 16;
        int pa = W + r, pb = W + r + 8;
        int swa = ((pa >> 3) & 15) ^ (r << 1);
        int swb2 = ((pb >> 3) & 15) ^ (r << 1);
        int A0 = sA[pa * 16 + (q ^ swa)];
        int A1 = sA[pb * 16 + (q ^ swb2)];
        int A2 = sA[pa * 16 + ((q + 4) ^ swa)];
        int A3 = sA[pb * 16 + ((q + 4) ^ swb2)];
        int A4 = sA[pa * 16 + ((q + 8) ^ swa)];
        int A5 = sA[pb * 16 + ((q + 8) ^ swb2)];
        int A6 = sA[pa * 16 + ((q + 12) ^ swa)];
        int A7 = sA[pb * 16 + ((q + 12) ^ swb2)];

        int mtx = lane >> 3, jj = lane & 7;
        int pxm = W + ((mtx & 1) << 3);
        unsigned sCbase = (unsigned)__cvta_generic_to_shared(sC);

        #pragma unroll
        for (int nt = 0; nt < 8; nt += 2) {
            unsigned hr[4];
            #pragma unroll
            for (int h = 0; h < 2; h++) {
                const int4& B = Bf[nt + h];
                int c0 = 0, c1 = 0, c2 = 0, c3 = 0;
                asm("mma.sync.aligned.m16n8k32.row.col.s32.s8.s8.s32 "
                    "{%0,%1,%2,%3}, {%4,%5,%6,%7}, {%8,%9}, {%0,%1,%2,%3};"
                    : "+r"(c0), "+r"(c1), "+r"(c2), "+r"(c3)
                    : "r"(A0), "r"(A1), "r"(A2), "r"(A3), "r"(B.x), "r"(B.y));
                asm("mma.sync.aligned.m16n8k32.row.col.s32.s8.s8.s32 "
                    "{%0,%1,%2,%3}, {%4,%5,%6,%7}, {%8,%9}, {%0,%1,%2,%3};"
                    : "+r"(c0), "+r"(c1), "+r"(c2), "+r"(c3)
                    : "r"(A4), "r"(A5), "r"(A6), "r"(A7), "r"(B.z), "r"(B.w));
                float y0 = (float)c0 * osc, y1 = (float)c1 * osc;
                float y2 = (float)c2 * osc, y3 = (float)c3 * osc;
                lmax = fmaxf(lmax, fmaxf(fmaxf(fabsf(y0), fabsf(y1)),
                                         fmaxf(fabsf(y2), fabsf(y3))));
                __half2 h01 = __floats2half2_rn(y0, y1);
                __half2 h23 = __floats2half2_rn(y2, y3);
                hr[h * 2 + 0] = *reinterpret_cast<unsigned*>(&h01);
                hr[h * 2 + 1] = *reinterpret_cast<unsigned*>(&h23);
            }
            int com = (nt + (mtx >> 1)) * 8 + jj;
            unsigned saddr = sCbase + (unsigned)((com * SCP + pxm) * 2);
            asm volatile("stmatrix.sync.aligned.m8n8.x4.trans.shared.b16 "
                         "[%0], {%1, %2, %3, %4};"
                         :: "r"(saddr), "r"(hr[0]), "r"(hr[1]), "r"(hr[2]), "r"(hr[3]));
        }
    }
    __syncthreads();

    // ---- stage 3: vectorized [co][px] copy to gmem ---------------------------
    {
        int co = t >> 2, jx = t & 3;
        unsigned gb = bbase + (unsigned)co * HW;
        #pragma unroll
        for (int it = 0; it < 4; it++) {
            int pxo = jx * 8 + it * 32;
            uint4 v = *reinterpret_cast<const uint4*>(&sC[co * SCP + pxo]);
            *reinterpret_cast<uint4*>(g_bufA + gb + pxo) = v;
        }
    }

    // ---- amax reduction ------------------------------------------------------
    #pragma unroll
    for (int off = 16; off; off >>= 1) lmax = fmaxf(lmax, __shfl_xor_sync(0xFFFFFFFFu, lmax, off));
    __shared__ float wm[8];
    int wid = t >> 5;
    if (lane == 0) wm[wid] = lmax;
    __syncthreads();
    if (t == 0) {
        float mm = wm[0];
        #pragma unroll
        for (int i = 1; i < 8; i++) mm = fmaxf(mm, wm[i]);
        atomicMax(&g_amax[WHICH * 2 + 1], __float_as_uint(mm));
    }
}

// ---------------- depthwise 3x3 (exact int8 dp4a) + PReLU (+residual) --------
// WHICH 0: bufA(half) -> bufB(half), amax_in [1], fused amax_out [2]
// WHICH 1: bufA(half) -> dout(fp32) + residual bufC(half x), amax_in [3]
template<int WHICH>
__global__ void __launch_bounds__(128) k_dw(float* __restrict__ dout,
                                            const float* __restrict__ alpha)
{
    int bc    = blockIdx.x >> 2;     // 0..1023
    int strip = blockIdx.x & 3;
    int c     = bc & 63;
    int warp  = threadIdx.x >> 5;
    int lane  = threadIdx.x & 31;
    int rbase = strip * 64 + warp * 16;
    int col0  = lane * 8;

    float in_max = __uint_as_float(g_amax[WHICH == 0 ? 1 : 3]);
    float s_in = in_max * (1.0f / 127.0f) + 1e-12f;
    float inv  = 1.0f / s_in;
    float osc  = s_in * g_wscale[WHICH == 0 ? 1 : 3];   // int acc -> fp value

    int wr0 = g_qwfi[WHICH][c * 3 + 0];
    int wr1 = g_qwfi[WHICH][c * 3 + 1];
    int wr2 = g_qwfi[WHICH][c * 3 + 2];
    float a = alpha[c];

    const __half* in = g_bufA + (unsigned)bc * HW;
    int accT[8], accM[8];
    #pragma unroll
    for (int j = 0; j < 8; j++) { accT[j] = 0; accM[j] = 0; }
    float lmax = 0.f;

    uint4 nxt;
    {
        int rr = rbase - 1;
        nxt = (rr >= 0) ? *reinterpret_cast<const uint4*>(in + rr * 256 + col0)
                        : make_uint4(0, 0, 0, 0);
    }

    #pragma unroll 3
    for (int k = 0; k < 18; k++) {
        uint4 raw = nxt;
        int rr = rbase - 1 + k;
        bool valid = (rr >= 0 && rr < 256);
        if (k < 17) {                      // prefetch next row
            int rn = rbase + k;
            nxt = (rn < 256) ? *reinterpret_cast<const uint4*>(in + rn * 256 + col0)
                             : make_uint4(0, 0, 0, 0);
        }

        unsigned wA = 0, wB = 0;
        if (valid) {
            float2 f0 = __half22float2(*reinterpret_cast<__half2*>(&raw.x));
            float2 f1 = __half22float2(*reinterpret_cast<__half2*>(&raw.y));
            float2 f2 = __half22float2(*reinterpret_cast<__half2*>(&raw.z));
            float2 f3 = __half22float2(*reinterpret_cast<__half2*>(&raw.w));
            int q0 = __float2int_rn(f0.x * inv), q1 = __float2int_rn(f0.y * inv);
            int q2 = __float2int_rn(f1.x * inv), q3 = __float2int_rn(f1.y * inv);
            int q4 = __float2int_rn(f2.x * inv), q5 = __float2int_rn(f2.y * inv);
            int q6 = __float2int_rn(f3.x * inv), q7 = __float2int_rn(f3.y * inv);
            wA = __byte_perm(__byte_perm(q0, q1, 0x0040),
                             __byte_perm(q2, q3, 0x0040), 0x5410);
            wB = __byte_perm(__byte_perm(q4, q5, 0x0040),
                             __byte_perm(q6, q7, 0x0040), 0x5410);
        }
        unsigned wPrev = __shfl_up_sync(0xFFFFFFFFu, wB, 1);
        unsigned wNext = __shfl_down_sync(0xFFFFFFFFu, wA, 1);
        if (lane == 0)  wPrev = 0;    // image left edge
        if (lane == 31) wNext = 0;    // image right edge

        unsigned win[8];
        win[0] = __byte_perm(wPrev, wA, 0x0543);
        win[1] = wA;
        win[2] = __byte_perm(wA, wB, 0x4321);
        win[3] = __byte_perm(wA, wB, 0x5432);
        win[4] = __byte_perm(wA, wB, 0x6543);
        win[5] = wB;
        win[6] = __byte_perm(wB, wNext, 0x4321);
        win[7] = __byte_perm(wB, wNext, 0x5432);

        if (k >= 2) {
            int ro = rbase + k - 2;
            unsigned off = (unsigned)bc * HW + (unsigned)(ro * 256 + col0);
            float y[8];
            #pragma unroll
            for (int j = 0; j < 8; j++) {
                int acc = __dp4a((int)win[j], wr2, accM[j]);
                float v = (float)acc * osc;
                y[j] = (v > 0.f) ? v : a * v;
            }
            if (WHICH == 0) {
                #pragma unroll
                for (int j = 0; j < 8; j++) lmax = fmaxf(lmax, fabsf(y[j]));
                uint4 st;
                __half2 h0 = __floats2half2_rn(y[0], y[1]);
                __half2 h1 = __floats2half2_rn(y[2], y[3]);
                __half2 h2 = __floats2half2_rn(y[4], y[5]);
                __half2 h3 = __floats2half2_rn(y[6], y[7]);
                st.x = *reinterpret_cast<unsigned*>(&h0);
                st.y = *reinterpret_cast<unsigned*>(&h1);
                st.z = *reinterpret_cast<unsigned*>(&h2);
                st.w = *reinterpret_cast<unsigned*>(&h3);
                *reinterpret_cast<uint4*>(g_bufB + off) = st;
            } else {
                uint4 rr16 = *reinterpret_cast<const uint4*>(g_bufC + off);
                float2 r0 = __half22float2(*reinterpret_cast<__half2*>(&rr16.x));
                float2 r1 = __half22float2(*reinterpret_cast<__half2*>(&rr16.y));
                float2 r2 = __half22float2(*reinterpret_cast<__half2*>(&rr16.z));
                float2 r3 = __half22float2(*reinterpret_cast<__half2*>(&rr16.w));
                float4 o0, o1;
                o0.x = y[0] + r0.x; o0.y = y[1] + r0.y;
                o0.z = y[2] + r1.x; o0.w = y[3] + r1.y;
                o1.x = y[4] + r2.x; o1.y = y[5] + r2.y;
                o1.z = y[6] + r3.x; o1.w = y[7] + r3.y;
                __stcs(reinterpret_cast<float4*>(dout + off), o0);
                __stcs(reinterpret_cast<float4*>(dout + off + 4), o1);
            }
        }
        #pragma unroll
        for (int j = 0; j < 8; j++) {
            accM[j] = __dp4a((int)win[j], wr1, accT[j]);
            accT[j] = __dp4a((int)win[j], wr0, 0);
        }
    }

    if (WHICH == 0) {
        #pragma unroll
        for (int off = 16; off; off >>= 1) lmax = fmaxf(lmax, __shfl_xor_sync(0xFFFFFFFFu, lmax, off));
        __shared__ float wm[4];
        if (lane == 0) wm[warp] = lmax;
        __syncthreads();
        if (threadIdx.x == 0)
            atomicMax(&g_amax[2],
                      __float_as_uint(fmaxf(fmaxf(wm[0], wm[1]), fmaxf(wm[2], wm[3]))));
    }
}

// ---------------- launch ------------------------------------------------------
extern "C" void kernel_launch(void* const* d_in, const int* in_sizes, int n_in,
                              void* d_out, int out_size)
{
    const float* x      = (const float*)d_in[0];
    const float* w_p1   = (const float*)d_in[1];
    const float* w_f1   = (const float*)d_in[2];
    const float* w_p2   = (const float*)d_in[3];
    const float* w_f2   = (const float*)d_in[4];
    const float* alpha1 = (const float*)d_in[5];
    const float* alpha2 = (const float*)d_in[6];
    float* out = (float*)d_out;

    k_init<<<2052, 256>>>((const float4*)x, NTOT / 4, w_p1, w_f1, w_p2, w_f2);

    k_pw<0><<<NPIX / 128, 256>>>();              // bufC -> bufA, amax y1
    k_dw<0><<<4096, 128>>>(nullptr, alpha1);     // bufA -> bufB, amax y3
    k_pw<1><<<NPIX / 128, 256>>>();              // bufB -> bufA, amax y4
    k_dw<1><<<4096, 128>>>(out, alpha2);         // bufA -> out (+x16)
}

// round 11
// speedup vs baseline: 1.2520x; 1.0076x over previous
#include <cuda_runtime.h>
#include <cuda_fp16.h>
#include <cstdint>

#define HW    65536
#define CCH   64
#define NPIX  (16 * HW)            // 1,048,576 pixels
#define NTOT  (16 * CCH * HW)      // 67,108,864 elements

// ---------------- device scratch (allocation-free) ---------------------------
__device__ __half   g_bufA[NTOT];
__device__ __half   g_bufB[NTOT];
__device__ __half   g_bufC[NTOT];     // fp16 shadow of x
__device__ unsigned g_amax[4];        // abs-max bits of: x, y1, y3, y4 (idempotent)
__device__ float    g_wscale[4];      // scales of: w_p1, w_f1, w_p2, w_f2
__device__ int      g_qwp[2][1024];   // pw weights in IMMA B-fragment order
__device__ int      g_qwfi[2][192];   // packed int8 dw weight rows [c][3] = (w0,w1,w2,0)

// ---------------- init: weight prep (blocks 0-3) + absmax/x16 (rest) ---------
__global__ void __launch_bounds__(256) k_init(const float4* __restrict__ x, int nvec,
                                              const float* __restrict__ wp1,
                                              const float* __restrict__ wf1,
                                              const float* __restrict__ wp2,
                                              const float* __restrict__ wf2)
{
    if (blockIdx.x < 4) {
        int b = blockIdx.x;   // 0:wp1 1:wf1 2:wp2 3:wf2
        const float* w = (b == 0) ? wp1 : (b == 1) ? wf1 : (b == 2) ? wp2 : wf2;
        int n = (b & 1) ? 576 : 4096;

        __shared__ float red[256];
        float m = 0.f;
        for (int i = threadIdx.x; i < n; i += 256) m = fmaxf(m, fabsf(w[i]));
        red[threadIdx.x] = m;
        __syncthreads();
        for (int s = 128; s > 0; s >>= 1) {
            if (threadIdx.x < s) red[threadIdx.x] = fmaxf(red[threadIdx.x], red[threadIdx.x + s]);
            __syncthreads();
        }
        __shared__ float s_scale;
        if (threadIdx.x == 0) {
            float sc = red[0] / 7.0f + 1e-12f;
            g_wscale[b] = sc;
            s_scale = sc;
        }
        __syncthreads();
        float sc = s_scale;

        if (b & 1) {
            for (int i = threadIdx.x; i < 192; i += 256) {
                const float* wr = w + (i / 3) * 9 + (i % 3) * 3;
                int q0 = (int)fminf(fmaxf(rintf(wr[0] / sc), -7.f), 7.f);
                int q1 = (int)fminf(fmaxf(rintf(wr[1] / sc), -7.f), 7.f);
                int q2 = (int)fminf(fmaxf(rintf(wr[2] / sc), -7.f), 7.f);
                g_qwfi[b >> 1][i] = (q0 & 0xFF) | ((q1 & 0xFF) << 8) | ((q2 & 0xFF) << 16);
            }
        } else {
            // pointwise: pack words and store in IMMA B-fragment order:
            // idx = nt*128 + (r*4+q)*4 + m  for co = nt*8+r, kw = q+4m
            for (int i = threadIdx.x; i < 1024; i += 256) {
                int word = 0;
                #pragma unroll
                for (int j = 0; j < 4; j++) {
                    float q = fminf(fmaxf(rintf(w[i * 4 + j] / sc), -7.f), 7.f);
                    word |= ((int)q & 0xFF) << (8 * j);
                }
                int co = i >> 4, kw = i & 15;
                int nt = co >> 3, rr = co & 7, qq = kw & 3, mm = kw >> 2;
                g_qwp[b >> 1][nt * 128 + (rr * 4 + qq) * 4 + mm] = word;
            }
        }
        return;
    }

    // ---- absmax(x) + fp16 shadow copy ----
    uint2* __restrict__ c16 = reinterpret_cast<uint2*>(g_bufC);
    int stride = (gridDim.x - 4) * 256;
    float m = 0.f;
    for (int i = (blockIdx.x - 4) * 256 + threadIdx.x; i < nvec; i += stride) {
        float4 v = __ldcs(&x[i]);
        __half2 h01 = __floats2half2_rn(v.x, v.y);
        __half2 h23 = __floats2half2_rn(v.z, v.w);
        uint2 st;
        st.x = *reinterpret_cast<unsigned*>(&h01);
        st.y = *reinterpret_cast<unsigned*>(&h23);
        c16[i] = st;
        m = fmaxf(m, fmaxf(fmaxf(fabsf(v.x), fabsf(v.y)), fmaxf(fabsf(v.z), fabsf(v.w))));
    }
    #pragma unroll
    for (int off = 16; off; off >>= 1) m = fmaxf(m, __shfl_xor_sync(0xFFFFFFFFu, m, off));
    __shared__ float wm[8];
    int lane = threadIdx.x & 31, wid = threadIdx.x >> 5;
    if (lane == 0) wm[wid] = m;
    __syncthreads();
    if (threadIdx.x == 0) {
        float mm = wm[0];
        #pragma unroll
        for (int i = 1; i < 8; i++) mm = fmaxf(mm, wm[i]);
        atomicMax(&g_amax[0], __float_as_uint(mm));
    }
}

// ---------------- pointwise 1x1 conv via tensor-core IMMA --------------------
// WHICH 0: in = bufC (half x), out = bufA (half), amax 0 -> 1
// WHICH 1: in = bufB (half),   out = bufA (half), amax 2 -> 3
// 256 thr / 128 px per block. Warp w: px tile [16w, 16w+16).
// sA: [px][kw] XOR-swizzled; B streamed from L1 (depth-2 pipeline);
// C: stmatrix.trans -> sC [co][px] pitch 136, then vectorized gmem copy.
#define SCP 136
template<int WHICH>
__global__ void __launch_bounds__(256, 5) k_pw()
{
    __shared__ __align__(16) int sA[128 * 16];                 // 8 KB
    __shared__ __align__(16) unsigned short sC[64 * SCP];      // 17408 B

    int t = threadIdx.x;
    int lane = t & 31;

    float in_max = __uint_as_float(g_amax[WHICH * 2]);
    float s_in = in_max * (1.0f / 127.0f) + 1e-12f;
    float inv  = 1.0f / s_in;
    float osc  = s_in * g_wscale[WHICH * 2];

    unsigned pxg  = blockIdx.x * 128u;
    unsigned bbase = (pxg >> 16) * (CCH * HW) + (pxg & 0xFFFFu);
    const __half* in = (WHICH == 0) ? g_bufC : g_bufB;

    // ---- stage 1: load fp16, quantize, transpose 4ch x 8px, swizzled store --
    {
        int cg = t >> 4;            // channel group 0..15
        int i15 = t & 15;
        int ps = i15 << 3;          // px 0..120 step 8
        int swb = cg ^ i15;
        unsigned Wlo[4], Whi[4];
        #pragma unroll
        for (int j = 0; j < 4; j++) {
            uint4 raw = *reinterpret_cast<const uint4*>(in + bbase + (unsigned)(4 * cg + j) * HW + ps);
            float2 f0 = __half22float2(*reinterpret_cast<__half2*>(&raw.x));
            float2 f1 = __half22float2(*reinterpret_cast<__half2*>(&raw.y));
            float2 f2 = __half22float2(*reinterpret_cast<__half2*>(&raw.z));
            float2 f3 = __half22float2(*reinterpret_cast<__half2*>(&raw.w));
            int q0 = __float2int_rn(f0.x * inv), q1 = __float2int_rn(f0.y * inv);
            int q2 = __float2int_rn(f1.x * inv), q3 = __float2int_rn(f1.y * inv);
            int q4 = __float2int_rn(f2.x * inv), q5 = __float2int_rn(f2.y * inv);
            int q6 = __float2int_rn(f3.x * inv), q7 = __float2int_rn(f3.y * inv);
            Wlo[j] = __byte_perm(__byte_perm(q0, q1, 0x0040),
                                 __byte_perm(q2, q3, 0x0040), 0x5410);
            Whi[j] = __byte_perm(__byte_perm(q4, q5, 0x0040),
                                 __byte_perm(q6, q7, 0x0040), 0x5410);
        }
        unsigned X01 = __byte_perm(Wlo[0], Wlo[1], 0x5140);
        unsigned X23 = __byte_perm(Wlo[2], Wlo[3], 0x5140);
        unsigned Y01 = __byte_perm(Wlo[0], Wlo[1], 0x7362);
        unsigned Y23 = __byte_perm(Wlo[2], Wlo[3], 0x7362);
        sA[(ps + 0) * 16 + (swb ^ 0)]  = __byte_perm(X01, X23, 0x5410);
        sA[(ps + 1) * 16 + (swb ^ 2)]  = __byte_perm(X01, X23, 0x7632);
        sA[(ps + 2) * 16 + (swb ^ 4)]  = __byte_perm(Y01, Y23, 0x5410);
        sA[(ps + 3) * 16 + (swb ^ 6)]  = __byte_perm(Y01, Y23, 0x7632);
        X01 = __byte_perm(Whi[0], Whi[1], 0x5140);
        X23 = __byte_perm(Whi[2], Whi[3], 0x5140);
        Y01 = __byte_perm(Whi[0], Whi[1], 0x7362);
        Y23 = __byte_perm(Whi[2], Whi[3], 0x7362);
        sA[(ps + 4) * 16 + (swb ^ 8)]  = __byte_perm(X01, X23, 0x5410);
        sA[(ps + 5) * 16 + (swb ^ 10)] = __byte_perm(X01, X23, 0x7632);
        sA[(ps + 6) * 16 + (swb ^ 12)] = __byte_perm(Y01, Y23, 0x5410);
        sA[(ps + 7) * 16 + (swb ^ 14)] = __byte_perm(Y01, Y23, 0x7632);
    }
    __syncthreads();

    // ---- stage 2: IMMA (B streamed from L1) + stmatrix.trans epilogue -------
    float lmax = 0.f;
    {
        int w = t >> 5;
        int r = lane >> 2, q = lane & 3;
        int W = w * 16;
        int pa = W + r, pb = W + r + 8;
        int swa = ((pa >> 3) & 15) ^ (r << 1);
        int swb2 = ((pb >> 3) & 15) ^ (r << 1);
        int A0 = sA[pa * 16 + (q ^ swa)];
        int A1 = sA[pb * 16 + (q ^ swb2)];
        int A2 = sA[pa * 16 + ((q + 4) ^ swa)];
        int A3 = sA[pb * 16 + ((q + 4) ^ swb2)];
        int A4 = sA[pa * 16 + ((q + 8) ^ swa)];
        int A5 = sA[pb * 16 + ((q + 8) ^ swb2)];
        int A6 = sA[pa * 16 + ((q + 12) ^ swa)];
        int A7 = sA[pb * 16 + ((q + 12) ^ swb2)];

        int mtx = lane >> 3, jj = lane & 7;
        int pxm = W + ((mtx & 1) << 3);
        unsigned sCbase = (unsigned)__cvta_generic_to_shared(sC);

        // depth-2 B-fragment stream (L1-hot, broadcast across warps/blocks)
        const int4* bfp = reinterpret_cast<const int4*>(g_qwp[WHICH]);
        int4 Bcur = __ldg(&bfp[lane]);
        int4 Bnxt = __ldg(&bfp[32 + lane]);

        #pragma unroll
        for (int nt = 0; nt < 8; nt += 2) {
            unsigned hr[4];
            #pragma unroll
            for (int h = 0; h < 2; h++) {
                int4 B = (h == 0) ? Bcur : Bnxt;
                int c0 = 0, c1 = 0, c2 = 0, c3 = 0;
                asm("mma.sync.aligned.m16n8k32.row.col.s32.s8.s8.s32 "
                    "{%0,%1,%2,%3}, {%4,%5,%6,%7}, {%8,%9}, {%0,%1,%2,%3};"
                    : "+r"(c0), "+r"(c1), "+r"(c2), "+r"(c3)
                    : "r"(A0), "r"(A1), "r"(A2), "r"(A3), "r"(B.x), "r"(B.y));
                asm("mma.sync.aligned.m16n8k32.row.col.s32.s8.s8.s32 "
                    "{%0,%1,%2,%3}, {%4,%5,%6,%7}, {%8,%9}, {%0,%1,%2,%3};"
                    : "+r"(c0), "+r"(c1), "+r"(c2), "+r"(c3)
                    : "r"(A4), "r"(A5), "r"(A6), "r"(A7), "r"(B.z), "r"(B.w));
                float y0 = (float)c0 * osc, y1 = (float)c1 * osc;
                float y2 = (float)c2 * osc, y3 = (float)c3 * osc;
                lmax = fmaxf(lmax, fmaxf(fmaxf(fabsf(y0), fabsf(y1)),
                                         fmaxf(fabsf(y2), fabsf(y3))));
                __half2 h01 = __floats2half2_rn(y0, y1);
                __half2 h23 = __floats2half2_rn(y2, y3);
                hr[h * 2 + 0] = *reinterpret_cast<unsigned*>(&h01);
                hr[h * 2 + 1] = *reinterpret_cast<unsigned*>(&h23);
            }
            if (nt < 6) {
                Bcur = __ldg(&bfp[(nt + 2) * 32 + lane]);
                Bnxt = __ldg(&bfp[(nt + 3) * 32 + lane]);
            }
            int com = (nt + (mtx >> 1)) * 8 + jj;
            unsigned saddr = sCbase + (unsigned)((com * SCP + pxm) * 2);
            asm volatile("stmatrix.sync.aligned.m8n8.x4.trans.shared.b16 "
                         "[%0], {%1, %2, %3, %4};"
                         :: "r"(saddr), "r"(hr[0]), "r"(hr[1]), "r"(hr[2]), "r"(hr[3]));
        }
    }
    __syncthreads();

    // ---- stage 3: vectorized [co][px] copy to gmem ---------------------------
    {
        int co = t >> 2, jx = t & 3;
        unsigned gb = bbase + (unsigned)co * HW;
        #pragma unroll
        for (int it = 0; it < 4; it++) {
            int pxo = jx * 8 + it * 32;
            uint4 v = *reinterpret_cast<const uint4*>(&sC[co * SCP + pxo]);
            *reinterpret_cast<uint4*>(g_bufA + gb + pxo) = v;
        }
    }

    // ---- amax reduction ------------------------------------------------------
    #pragma unroll
    for (int off = 16; off; off >>= 1) lmax = fmaxf(lmax, __shfl_xor_sync(0xFFFFFFFFu, lmax, off));
    __shared__ float wm[8];
    int wid = t >> 5;
    if (lane == 0) wm[wid] = lmax;
    __syncthreads();
    if (t == 0) {
        float mm = wm[0];
        #pragma unroll
        for (int i = 1; i < 8; i++) mm = fmaxf(mm, wm[i]);
        atomicMax(&g_amax[WHICH * 2 + 1], __float_as_uint(mm));
    }
}

// ---------------- depthwise 3x3 (exact int8 dp4a) + PReLU (+residual) --------
// WHICH 0: bufA(half) -> bufB(half), amax_in [1], fused amax_out [2]
// WHICH 1: bufA(half) -> dout(fp32) + residual bufC(half x), amax_in [3]
template<int WHICH>
__global__ void __launch_bounds__(128) k_dw(float* __restrict__ dout,
                                            const float* __restrict__ alpha)
{
    int bc    = blockIdx.x >> 2;     // 0..1023
    int strip = blockIdx.x & 3;
    int c     = bc & 63;
    int warp  = threadIdx.x >> 5;
    int lane  = threadIdx.x & 31;
    int rbase = strip * 64 + warp * 16;
    int col0  = lane * 8;

    float in_max = __uint_as_float(g_amax[WHICH == 0 ? 1 : 3]);
    float s_in = in_max * (1.0f / 127.0f) + 1e-12f;
    float inv  = 1.0f / s_in;
    float osc  = s_in * g_wscale[WHICH == 0 ? 1 : 3];   // int acc -> fp value

    int wr0 = g_qwfi[WHICH][c * 3 + 0];
    int wr1 = g_qwfi[WHICH][c * 3 + 1];
    int wr2 = g_qwfi[WHICH][c * 3 + 2];
    float a = alpha[c];

    const __half* in = g_bufA + (unsigned)bc * HW;
    int accT[8], accM[8];
    #pragma unroll
    for (int j = 0; j < 8; j++) { accT[j] = 0; accM[j] = 0; }
    float lmax = 0.f;

    uint4 nxt;
    {
        int rr = rbase - 1;
        nxt = (rr >= 0) ? *reinterpret_cast<const uint4*>(in + rr * 256 + col0)
                        : make_uint4(0, 0, 0, 0);
    }

    #pragma unroll 3
    for (int k = 0; k < 18; k++) {
        uint4 raw = nxt;
        int rr = rbase - 1 + k;
        bool valid = (rr >= 0 && rr < 256);
        if (k < 17) {                      // prefetch next row
            int rn = rbase + k;
            nxt = (rn < 256) ? *reinterpret_cast<const uint4*>(in + rn * 256 + col0)
                             : make_uint4(0, 0, 0, 0);
        }

        unsigned wA = 0, wB = 0;
        if (valid) {
            float2 f0 = __half22float2(*reinterpret_cast<__half2*>(&raw.x));
            float2 f1 = __half22float2(*reinterpret_cast<__half2*>(&raw.y));
            float2 f2 = __half22float2(*reinterpret_cast<__half2*>(&raw.z));
            float2 f3 = __half22float2(*reinterpret_cast<__half2*>(&raw.w));
            int q0 = __float2int_rn(f0.x * inv), q1 = __float2int_rn(f0.y * inv);
            int q2 = __float2int_rn(f1.x * inv), q3 = __float2int_rn(f1.y * inv);
            int q4 = __float2int_rn(f2.x * inv), q5 = __float2int_rn(f2.y * inv);
            int q6 = __float2int_rn(f3.x * inv), q7 = __float2int_rn(f3.y * inv);
            wA = __byte_perm(__byte_perm(q0, q1, 0x0040),
                             __byte_perm(q2, q3, 0x0040), 0x5410);
            wB = __byte_perm(__byte_perm(q4, q5, 0x0040),
                             __byte_perm(q6, q7, 0x0040), 0x5410);
        }
        unsigned wPrev = __shfl_up_sync(0xFFFFFFFFu, wB, 1);
        unsigned wNext = __shfl_down_sync(0xFFFFFFFFu, wA, 1);
        if (lane == 0)  wPrev = 0;    // image left edge
        if (lane == 31) wNext = 0;    // image right edge

        unsigned win[8];
        win[0] = __byte_perm(wPrev, wA, 0x0543);
        win[1] = wA;
        win[2] = __byte_perm(wA, wB, 0x4321);
        win[3] = __byte_perm(wA, wB, 0x5432);
        win[4] = __byte_perm(wA, wB, 0x6543);
        win[5] = wB;
        win[6] = __byte_perm(wB, wNext, 0x4321);
        win[7] = __byte_perm(wB, wNext, 0x5432);

        if (k >= 2) {
            int ro = rbase + k - 2;
            unsigned off = (unsigned)bc * HW + (unsigned)(ro * 256 + col0);
            float y[8];
            #pragma unroll
            for (int j = 0; j < 8; j++) {
                int acc = __dp4a((int)win[j], wr2, accM[j]);
                float v = (float)acc * osc;
                y[j] = (v > 0.f) ? v : a * v;
            }
            if (WHICH == 0) {
                #pragma unroll
                for (int j = 0; j < 8; j++) lmax = fmaxf(lmax, fabsf(y[j]));
                uint4 st;
                __half2 h0 = __floats2half2_rn(y[0], y[1]);
                __half2 h1 = __floats2half2_rn(y[2], y[3]);
                __half2 h2 = __floats2half2_rn(y[4], y[5]);
                __half2 h3 = __floats2half2_rn(y[6], y[7]);
                st.x = *reinterpret_cast<unsigned*>(&h0);
                st.y = *reinterpret_cast<unsigned*>(&h1);
                st.z = *reinterpret_cast<unsigned*>(&h2);
                st.w = *reinterpret_cast<unsigned*>(&h3);
                *reinterpret_cast<uint4*>(g_bufB + off) = st;
            } else {
                uint4 rr16 = *reinterpret_cast<const uint4*>(g_bufC + off);
                float2 r0 = __half22float2(*reinterpret_cast<__half2*>(&rr16.x));
                float2 r1 = __half22float2(*reinterpret_cast<__half2*>(&rr16.y));
                float2 r2 = __half22float2(*reinterpret_cast<__half2*>(&rr16.z));
                float2 r3 = __half22float2(*reinterpret_cast<__half2*>(&rr16.w));
                float4 o0, o1;
                o0.x = y[0] + r0.x; o0.y = y[1] + r0.y;
                o0.z = y[2] + r1.x; o0.w = y[3] + r1.y;
                o1.x = y[4] + r2.x; o1.y = y[5] + r2.y;
                o1.z = y[6] + r3.x; o1.w = y[7] + r3.y;
                __stcs(reinterpret_cast<float4*>(dout + off), o0);
                __stcs(reinterpret_cast<float4*>(dout + off + 4), o1);
            }
        }
        #pragma unroll
        for (int j = 0; j < 8; j++) {
            accM[j] = __dp4a((int)win[j], wr1, accT[j]);
            accT[j] = __dp4a((int)win[j], wr0, 0);
        }
    }

    if (WHICH == 0) {
        #pragma unroll
        for (int off = 16; off; off >>= 1) lmax = fmaxf(lmax, __shfl_xor_sync(0xFFFFFFFFu, lmax, off));
        __shared__ float wm[4];
        if (lane == 0) wm[warp] = lmax;
        __syncthreads();
        if (threadIdx.x == 0)
            atomicMax(&g_amax[2],
                      __float_as_uint(fmaxf(fmaxf(wm[0], wm[1]), fmaxf(wm[2], wm[3]))));
    }
}

// ---------------- launch ------------------------------------------------------
extern "C" void kernel_launch(void* const* d_in, const int* in_sizes, int n_in,
                              void* d_out, int out_size)
{
    const float* x      = (const float*)d_in[0];
    const float* w_p1   = (const float*)d_in[1];
    const float* w_f1   = (const float*)d_in[2];
    const float* w_p2   = (const float*)d_in[3];
    const float* w_f2   = (const float*)d_in[4];
    const float* alpha1 = (const float*)d_in[5];
    const float* alpha2 = (const float*)d_in[6];
    float* out = (float*)d_out;

    k_init<<<2052, 256>>>((const float4*)x, NTOT / 4, w_p1, w_f1, w_p2, w_f2);

    k_pw<0><<<NPIX / 128, 256>>>();              // bufC -> bufA, amax y1
    k_dw<0><<<4096, 128>>>(nullptr, alpha1);     // bufA -> bufB, amax y3
    k_pw<1><<<NPIX / 128, 256>>>();              // bufB -> bufA, amax y4
    k_dw<1><<<4096, 128>>>(out, alpha2);         // bufA -> out (+x16)
}